// round 2
// baseline (speedup 1.0000x reference)
#include <cuda_runtime.h>

#define N_NODES 100000
#define N_EDGES 1600000
#define IN_CH 128
#define HID 32

// ---------------- scratch (device globals: no allocation allowed) ----------
__device__ float g_y [N_NODES * HID];   // x @ w1a
__device__ float g_a1[N_NODES * HID];   // y + agg(y)
__device__ float g_u [N_NODES * HID];   // relu(a1+b1a) @ W12 + B12
__device__ float g_a2[N_NODES * HID];   // u + agg(u)
__device__ float g_t [N_NODES];         // relu(a2+b2a) . Wv + bv
__device__ int2  g_edges[N_EDGES];      // (src, dst) as int32
__device__ float g_W12[HID * HID];      // w1b @ w2a
__device__ float g_B12[HID];            // b1b @ w2a
__device__ float g_Wv [HID];            // w2b @ w3
__device__ float g_bv;                  // b2b . w3

// ---------------- tiny weight-fusion kernel (1 block) ----------------------
__global__ void prep_w(const float* __restrict__ w1b, const float* __restrict__ w2a,
                       const float* __restrict__ b1b, const float* __restrict__ w2b,
                       const float* __restrict__ w3,  const float* __restrict__ b2b) {
    int i = threadIdx.x >> 5;   // 0..31
    int j = threadIdx.x & 31;   // 0..31
    float s = 0.f;
    #pragma unroll
    for (int m = 0; m < HID; m++) s += w1b[i * HID + m] * w2a[m * HID + j];
    g_W12[i * HID + j] = s;
    if (i == 0) {
        float b = 0.f;
        #pragma unroll
        for (int m = 0; m < HID; m++) b += b1b[m] * w2a[m * HID + j];
        g_B12[j] = b;
        float wv = 0.f;
        #pragma unroll
        for (int m = 0; m < HID; m++) wv += w2b[j * HID + m] * w3[m];
        g_Wv[j] = wv;
        if (j == 0) {
            float bb = 0.f;
            #pragma unroll
            for (int m = 0; m < HID; m++) bb += b2b[m] * w3[m];
            g_bv = bb;
        }
    }
}

// ---------------- edge index (int32, JAX x64 disabled) -> packed int2 ------
__global__ void prep_e(const int* __restrict__ ei) {
    int e = blockIdx.x * blockDim.x + threadIdx.x;
    if (e < N_EDGES)
        g_edges[e] = make_int2(ei[e], ei[N_EDGES + e]);
}

// ---------------- K1: y = x @ w1a ; a1 = y (self term) ---------------------
// 256 threads handle 256 nodes x 32 channels; each thread: 4 nodes x 8 ch.
__global__ void __launch_bounds__(256) gemm1(const float* __restrict__ x,
                                             const float* __restrict__ w1a) {
    __shared__ float xs[256][33];     // padded to kill bank conflicts
    __shared__ float ws[HID * HID];   // 32(k) x 32(j) chunk of w1a
    const int tid   = threadIdx.x;
    const int node0 = blockIdx.x * 256;
    const int cb    = (tid & 3) * 8;  // channel base
    const int ng    = tid >> 2;       // node group (4 nodes)

    float acc[4][8];
    #pragma unroll
    for (int a = 0; a < 4; a++)
        #pragma unroll
        for (int c = 0; c < 8; c++) acc[a][c] = 0.f;

    for (int kc = 0; kc < IN_CH / 32; kc++) {
        __syncthreads();
        // ws chunk: 1024 floats = 256 float4
        ((float4*)ws)[tid] = ((const float4*)(w1a + kc * 32 * HID))[tid];
        // xs: 256 nodes x 32 floats = 2048 float4, 8 per thread (coalesced)
        #pragma unroll
        for (int i = 0; i < 8; i++) {
            int f    = tid + 256 * i;
            int node = f >> 3;
            int col4 = f & 7;
            int gn   = node0 + node;
            float4 v = make_float4(0.f, 0.f, 0.f, 0.f);
            if (gn < N_NODES)
                v = *(const float4*)(x + (long long)gn * IN_CH + kc * 32 + col4 * 4);
            float* d = &xs[node][col4 * 4];
            d[0] = v.x; d[1] = v.y; d[2] = v.z; d[3] = v.w;
        }
        __syncthreads();
        #pragma unroll
        for (int k = 0; k < 32; k++) {
            float xv[4];
            #pragma unroll
            for (int a = 0; a < 4; a++) xv[a] = xs[ng * 4 + a][k];
            #pragma unroll
            for (int c = 0; c < 8; c++) {
                float wv = ws[k * HID + cb + c];
                #pragma unroll
                for (int a = 0; a < 4; a++) acc[a][c] += xv[a] * wv;
            }
        }
    }
    #pragma unroll
    for (int a = 0; a < 4; a++) {
        int gn = node0 + ng * 4 + a;
        if (gn < N_NODES) {
            float4 v0 = make_float4(acc[a][0], acc[a][1], acc[a][2], acc[a][3]);
            float4 v1 = make_float4(acc[a][4], acc[a][5], acc[a][6], acc[a][7]);
            long long o = (long long)gn * HID + cb;
            *(float4*)(g_y  + o)     = v0;
            *(float4*)(g_y  + o + 4) = v1;
            *(float4*)(g_a1 + o)     = v0;
            *(float4*)(g_a1 + o + 4) = v1;
        }
    }
}

// ---------------- 32-channel edge aggregation (atomic float4) --------------
// which==0: a1 += y[src];  which==1: a2 += u[src]
__global__ void edge_agg32(int which) {
    const float* sf = which ? g_u  : g_y;
    float*       da = which ? g_a2 : g_a1;
    long long t = (long long)blockIdx.x * blockDim.x + threadIdx.x;
    if (t >= (long long)N_EDGES * 8) return;
    int e = (int)(t >> 3);
    int q = (int)(t & 7);
    int2 ed = g_edges[e];
    float4 v = ((const float4*)(sf + (long long)ed.x * HID))[q];
    atomicAdd(((float4*)(da + (long long)ed.y * HID)) + q, v);
}

// ---------------- K3: u = relu(a1+b1a) @ W12 + B12 ; a2 = u ---------------
// warp per node; W12 column held in registers, row broadcast via shfl.
__global__ void mlp12(const float* __restrict__ b1a) {
    int gw     = (blockIdx.x * blockDim.x + threadIdx.x) >> 5;
    int lane   = threadIdx.x & 31;
    int nwarps = (gridDim.x * blockDim.x) >> 5;
    float wcol[32];
    #pragma unroll
    for (int i = 0; i < 32; i++) wcol[i] = g_W12[i * HID + lane];
    float bb = g_B12[lane];
    float b1 = b1a[lane];
    for (int n = gw; n < N_NODES; n += nwarps) {
        float r = fmaxf(g_a1[(long long)n * HID + lane] + b1, 0.f);
        float u = bb;
        #pragma unroll
        for (int i = 0; i < 32; i++)
            u += __shfl_sync(0xffffffffu, r, i) * wcol[i];
        g_u [(long long)n * HID + lane] = u;
        g_a2[(long long)n * HID + lane] = u;
    }
}

// ---------------- K5: t = relu(a2+b2a).Wv + bv ; out = t + b3 -------------
__global__ void final_node(const float* __restrict__ b2a,
                           const float* __restrict__ b3,
                           float* __restrict__ out) {
    int gw     = (blockIdx.x * blockDim.x + threadIdx.x) >> 5;
    int lane   = threadIdx.x & 31;
    int nwarps = (gridDim.x * blockDim.x) >> 5;
    float wv  = g_Wv[lane];
    float b2  = b2a[lane];
    float bvv = g_bv;
    float b3v = b3[0];
    for (int n = gw; n < N_NODES; n += nwarps) {
        float r = fmaxf(g_a2[(long long)n * HID + lane] + b2, 0.f) * wv;
        #pragma unroll
        for (int o = 16; o > 0; o >>= 1)
            r += __shfl_xor_sync(0xffffffffu, r, o);
        if (lane == 0) {
            float tv = r + bvv;
            g_t[n]  = tv;
            out[n]  = tv + b3v;
        }
    }
}

// ---------------- K6: scalar edge aggregation into out --------------------
__global__ void edge_agg1(float* __restrict__ out) {
    int e = blockIdx.x * blockDim.x + threadIdx.x;
    if (e < N_EDGES) {
        int2 ed = g_edges[e];
        atomicAdd(out + ed.y, g_t[ed.x]);
    }
}

// ---------------- launch ---------------------------------------------------
extern "C" void kernel_launch(void* const* d_in, const int* in_sizes, int n_in,
                              void* d_out, int out_size) {
    const float* x   = (const float*)d_in[0];
    const int*   ei  = (const int*)d_in[1];
    const float* w1a = (const float*)d_in[2];
    const float* b1a = (const float*)d_in[3];
    const float* w1b = (const float*)d_in[4];
    const float* b1b = (const float*)d_in[5];
    const float* w2a = (const float*)d_in[6];
    const float* b2a = (const float*)d_in[7];
    const float* w2b = (const float*)d_in[8];
    const float* b2b = (const float*)d_in[9];
    const float* w3  = (const float*)d_in[10];
    const float* b3  = (const float*)d_in[11];
    float* out = (float*)d_out;

    prep_w<<<1, 1024>>>(w1b, w2a, b1b, w2b, w3, b2b);
    prep_e<<<(N_EDGES + 255) / 256, 256>>>(ei);
    gemm1<<<(N_NODES + 255) / 256, 256>>>(x, w1a);
    edge_agg32<<<(int)(((long long)N_EDGES * 8 + 255) / 256), 256>>>(0);
    mlp12<<<1563, 256>>>(b1a);
    edge_agg32<<<(int)(((long long)N_EDGES * 8 + 255) / 256), 256>>>(1);
    final_node<<<1563, 256>>>(b2a, b3, out);
    edge_agg1<<<(N_EDGES + 255) / 256, 256>>>(out);
}